// round 12
// baseline (speedup 1.0000x reference)
#include <cuda_runtime.h>
#include <cstdint>

#define HID      100
#define NREL     16
#define NBLK     5
#define CB       20
#define MAXN     100000
#define MAXRN    (NREL * MAXN)
#define MAXE     1600128      // >= ntiles*ETILE for E=1.6M
#define WSTRIDE  2004         // per-relation weight stride (2000 used + 4 pad)
#define ETILE    96
#define ETHREADS 480          // 15 warps: b = t/96 (0..4), warp-uniform

// ---------------- scratch (device globals; no allocations allowed) ----------------
__device__ int   g_cnt[MAXRN];      // per-(dst,rel) edge counts (key = dst*16+rel)
__device__ int   g_cursor[MAXRN];   // scatter cursors (exclusive prefix over keys)
__device__ int   g_part[2048];      // scan partials (<= 1563 blocks)
__device__ int4  g_edge[MAXE];      // key-sorted edges: {src, dst, rel, scale-bits}
__device__ float g_h1[MAXN * HID];  // layer-1 output (pre-relu)

// ---------------- helpers ----------------
__device__ __forceinline__ uint32_t smaddr(const void* p) {
    return (uint32_t)__cvta_generic_to_shared(p);
}
__device__ __forceinline__ void cpa16(uint32_t s, const void* g) {
    asm volatile("cp.async.cg.shared.global [%0], [%1], 16;" :: "r"(s), "l"(g));
}
#define CPA_COMMIT() asm volatile("cp.async.commit_group;" ::: "memory")
#define CPA_WAIT0()  asm volatile("cp.async.wait_group 0;" ::: "memory")

// ---------------- setup kernels ----------------
__global__ void k_zero(int RN, int E, int Epad) {
    int i = blockIdx.x * blockDim.x + threadIdx.x;
    if (i < RN) g_cnt[i] = 0;
    if (i < Epad - E) {                 // pad tail edges: inert (scale 0)
        g_edge[E + i] = make_int4(0, 0, 0, 0);
    }
}

__global__ void k_count(const int* __restrict__ eidx, const int* __restrict__ etyp,
                        int E) {
    int e = blockIdx.x * blockDim.x + threadIdx.x;
    if (e >= E) return;
    int dst = eidx[E + e];
    int rel = etyp[e];
    atomicAdd(&g_cnt[dst * NREL + rel], 1);
}

// ---------- 3-pass exclusive scan of g_cnt -> g_cursor (RN elements) ----------
__global__ void k_scan1(int RN) {
    __shared__ int sh[1024];
    int t = threadIdx.x;
    int i = blockIdx.x * 1024 + t;
    sh[t] = (i < RN) ? g_cnt[i] : 0;
    __syncthreads();
    for (int off = 512; off > 0; off >>= 1) {
        if (t < off) sh[t] += sh[t + off];
        __syncthreads();
    }
    if (t == 0) g_part[blockIdx.x] = sh[0];
}

__global__ void k_scan2(int nb) {       // 1 block, loops with carry
    __shared__ int sh[1024];
    __shared__ int s_carry;
    int t = threadIdx.x;
    if (t == 0) s_carry = 0;
    __syncthreads();
    for (int base = 0; base < nb; base += 1024) {
        int idx = base + t;
        int v = (idx < nb) ? g_part[idx] : 0;
        sh[t] = v;
        __syncthreads();
        for (int off = 1; off < 1024; off <<= 1) {
            int u = (t >= off) ? sh[t - off] : 0;
            __syncthreads();
            sh[t] += u;
            __syncthreads();
        }
        int carry = s_carry;
        if (idx < nb) g_part[idx] = carry + sh[t] - v;   // exclusive
        __syncthreads();
        if (t == 1023) s_carry = carry + sh[1023];
        __syncthreads();
    }
}

__global__ void k_scan3(int RN) {
    __shared__ int sh[1024];
    int t = threadIdx.x;
    int i = blockIdx.x * 1024 + t;
    int x = (i < RN) ? g_cnt[i] : 0;
    sh[t] = x;
    __syncthreads();
    for (int off = 1; off < 1024; off <<= 1) {
        int v = (t >= off) ? sh[t - off] : 0;
        __syncthreads();
        sh[t] += v;
        __syncthreads();
    }
    if (i < RN) g_cursor[i] = g_part[blockIdx.x] + sh[t] - x;
}

__global__ void k_scatter(const int* __restrict__ eidx, const int* __restrict__ etyp,
                          int E) {
    int e = blockIdx.x * blockDim.x + threadIdx.x;
    if (e >= E) return;
    int src = eidx[e];
    int dst = eidx[E + e];
    int rel = etyp[e];
    int key = dst * NREL + rel;
    int p = atomicAdd(&g_cursor[key], 1);
    int c = g_cnt[key];
    float sc = 1.0f / (float)(c > 1 ? c : 1);
    g_edge[p] = make_int4(src, dst, rel, __float_as_int(sc));
}

// ---------------- dense part: out = (relu?)x @ root + bias ----------------
#define GROWS 80
#define GTHREADS 256
__global__ __launch_bounds__(GTHREADS)
void k_init(const float* __restrict__ x, const float* __restrict__ root,
            const float* __restrict__ bias, float* __restrict__ out,
            int N, int do_relu) {
    extern __shared__ float sm_i[];
    float* xs = sm_i;                 // 80 * 101
    float* rs = sm_i + GROWS * 101;   // 100 * 100
    int t = threadIdx.x;
    int rowbase = blockIdx.x * GROWS;

    for (int i = t; i < HID * HID; i += GTHREADS) rs[i] = root[i];
    for (int i = t; i < GROWS * HID; i += GTHREADS) {
        int rr = i / HID, c = i - rr * HID;
        int row = rowbase + rr;
        float v = (row < N) ? x[row * HID + c] : 0.0f;
        if (do_relu) v = fmaxf(v, 0.0f);
        xs[rr * 101 + c] = v;
    }
    __syncthreads();
    if (t >= 250) return;

    int q = t % 25;
    int rg = t / 25;
    float4 b4 = *reinterpret_cast<const float4*>(bias + 4 * q);
    float acc[8][4];
#pragma unroll
    for (int i = 0; i < 8; i++) {
        acc[i][0] = b4.x; acc[i][1] = b4.y; acc[i][2] = b4.z; acc[i][3] = b4.w;
    }
#pragma unroll 4
    for (int k = 0; k < HID; k++) {
        float4 r4 = *reinterpret_cast<const float4*>(rs + k * HID + 4 * q);
#pragma unroll
        for (int i = 0; i < 8; i++) {
            float xv = xs[(rg * 8 + i) * 101 + k];
            acc[i][0] = fmaf(xv, r4.x, acc[i][0]);
            acc[i][1] = fmaf(xv, r4.y, acc[i][1]);
            acc[i][2] = fmaf(xv, r4.z, acc[i][2]);
            acc[i][3] = fmaf(xv, r4.w, acc[i][3]);
        }
    }
#pragma unroll
    for (int i = 0; i < 8; i++) {
        int row = rowbase + rg * 8 + i;
        if (row < N) {
            float4 o;
            o.x = acc[i][0]; o.y = acc[i][1]; o.z = acc[i][2]; o.w = acc[i][3];
            *reinterpret_cast<float4*>(out + row * HID + 4 * q) = o;
        }
    }
}

// ---------------- edge kernel ----------------
// Edges globally sorted by key = dst*16+rel. Per tile of 96 edges:
//   ballot pass: key-segment heads (~62), dst-groups (~8), per-warp rel
//   histogram of heads (for rel-sorted transform assignment).
//   phase A: warp per segment: sum raw x rows (relu+scale) -> head row (in place)
//   phase B: thread (b, e<nseg) transforms head row of rel-sorted segment
//            sseg[e] in place (weight LDS near-broadcast).
//   phase C: warp per dst-group: sum head rows, 100 atomics per dst.
// x rows staged in original order via cp.async 16B (double-buffered);
// meta triple-buffered.
__device__ __forceinline__ void stage_x(const float* __restrict__ x, const int4* md,
                                        float* xs, int t) {
#pragma unroll
    for (int k = 0; k < (ETILE * 25) / ETHREADS; k++) {   // 5
        int idx = t + k * ETHREADS;
        int j = idx / 25, c4 = idx - j * 25;
        int src = md[j].x;
        cpa16(smaddr(xs + j * 100 + c4 * 4), x + (size_t)src * HID + c4 * 4);
    }
}

__global__ __launch_bounds__(ETHREADS)
void k_edge(const float* __restrict__ x, const float* __restrict__ w,
            float* __restrict__ out, int ntiles, int do_relu) {
    extern __shared__ float sm_e[];
    float* ws      = sm_e;                             // 16*2004 floats
    float* xs0     = ws + NREL * WSTRIDE;              // 96*100
    float* xs1     = xs0 + ETILE * 100;                // 96*100
    int4*  mds     = (int4*)(xs1 + ETILE * 100);       // 3*96 int4
    int*   seghead = (int*)(mds + 3 * ETILE);          // 97
    int*   dsegs   = seghead + ETILE + 1;              // 97
    int*   sseg    = dsegs + ETILE + 1;                // 96
    int*   scnt    = sseg + ETILE;                     // 96 (3 warps x 32 rel-buckets)
    int*   sbase   = scnt + 96;                        // 96
    int*   swx     = sbase + 96;                       // 20

    int t = threadIdx.x;
    int lane = t & 31;
    int wrp = t >> 5;
    int b = t / ETILE;          // 0..4, warp-uniform
    int e = t - b * ETILE;      // 0..95

    for (int i = t; i < NREL * 2000; i += ETHREADS) {
        int r = i / 2000;
        ws[r * WSTRIDE + (i - r * 2000)] = w[i];
    }
    if (t < 96) scnt[t] = 0;

    int grid = gridDim.x;
    int tile0 = blockIdx.x;

    // ---- preloop: meta(t0); wait; stage x(t0); prefetch meta(t0+g) ----
    if (t < ETILE) cpa16(smaddr(mds + t), &g_edge[(size_t)tile0 * ETILE + t]);
    CPA_COMMIT();
    CPA_WAIT0();
    __syncthreads();
    stage_x(x, mds, xs0, t);
    CPA_COMMIT();
    if (tile0 + grid < ntiles && t < ETILE)
        cpa16(smaddr(mds + ETILE + t), &g_edge[(size_t)(tile0 + grid) * ETILE + t]);
    CPA_COMMIT();

    int par = 0, rot = 0;
    for (int tile = tile0; tile < ntiles; tile += grid) {
        CPA_WAIT0();                  // xs_c staged; meta(next) arrived
        __syncthreads();              // sync1

        int nxt = tile + grid;
        float* xs_c = par ? xs1 : xs0;
        float* xs_n = par ? xs0 : xs1;
        const int4* mdc = mds + rot * ETILE;
        const int4* mdn = mds + ((rot + 1) % 3) * ETILE;

        // issue staging of next tile + meta prefetch (async, overlaps below)
        if (nxt < ntiles) stage_x(x, mdn, xs_n, t);
        CPA_COMMIT();
        if (nxt + grid < ntiles && t < ETILE)
            cpa16(smaddr(mds + ((rot + 2) % 3) * ETILE + t),
                  &g_edge[(size_t)(nxt + grid) * ETILE + t]);
        CPA_COMMIT();

        // ---- phase 1: ballots (key heads, dst heads, rel histogram of heads) ----
        {
            bool kh = false, dh = false;
            int relk = 31;
            if (t < ETILE) {
                int4 cur = mdc[t];
                if (t == 0) { kh = true; dh = true; }
                else {
                    int4 prv = mdc[t - 1];
                    dh = (prv.y != cur.y);
                    kh = dh || (prv.z != cur.z);
                }
                relk = kh ? cur.z : 31;
                unsigned kb = __ballot_sync(0xFFFFFFFFu, kh);
                unsigned db = __ballot_sync(0xFFFFFFFFu, dh);
                unsigned m  = __match_any_sync(0xFFFFFFFFu, relk);
                if ((int)(__ffs(m) - 1) == lane) scnt[wrp * 32 + relk] = __popc(m);
                if (lane == 0) { swx[wrp] = __popc(kb); swx[4 + wrp] = __popc(db); }
            }
        }
        __syncthreads();              // sync2

        // ---- phase 2: prefixes ----
        if (t < 32) {
            int c0 = scnt[t], c1 = scnt[32 + t], c2 = scnt[64 + t];
            int tot = c0 + c1 + c2;
            int run = tot;
#pragma unroll
            for (int d = 1; d < 32; d <<= 1) {
                int v = __shfl_up_sync(0xFFFFFFFFu, run, d);
                if (lane >= d) run += v;
            }
            int off = run - tot;
            sbase[t] = off; sbase[32 + t] = off + c0; sbase[64 + t] = off + c0 + c1;
            if (t == 0) {
                int k0 = swx[0], k1 = swx[1], k2 = swx[2];
                int ns = k0 + k1 + k2;
                swx[8] = 0; swx[9] = k0; swx[10] = k0 + k1; swx[15] = ns;
                int d0 = swx[4], d1 = swx[5], d2 = swx[6];
                int nd = d0 + d1 + d2;
                swx[11] = 0; swx[12] = d0; swx[13] = d0 + d1; swx[16] = nd;
                seghead[ns] = ETILE;
                dsegs[nd] = ns;
            }
        }
        __syncthreads();              // sync3

        // ---- phase 3: scatter seghead / dsegs / sseg ----
        if (t < ETILE) {
            bool kh, dh;
            int relk;
            int4 cur = mdc[t];
            if (t == 0) { kh = true; dh = true; }
            else {
                int4 prv = mdc[t - 1];
                dh = (prv.y != cur.y);
                kh = dh || (prv.z != cur.z);
            }
            relk = kh ? cur.z : 31;
            unsigned kb = __ballot_sync(0xFFFFFFFFu, kh);
            unsigned db = __ballot_sync(0xFFFFFFFFu, dh);
            unsigned m  = __match_any_sync(0xFFFFFFFFu, relk);
            unsigned lt = (1u << lane) - 1u;
            int kr = swx[8 + wrp] + __popc(kb & lt);
            if (kh) {
                seghead[kr] = t;
                sseg[sbase[wrp * 32 + relk] + __popc(m & lt)] = kr;
            }
            if (dh) dsegs[swx[11 + wrp] + __popc(db & lt)] = kr;
        }
        __syncthreads();              // sync4

        int nseg = swx[15];
        int ndseg = swx[16];

        // ---- phase A: per-(dst,rel)-segment sum of raw rows -> head row ----
        if (t >= 192 && t < 288) scnt[t - 192] = 0;   // re-zero for next tile
        for (int s = wrp; s < nseg; s += ETHREADS / 32) {
            int a0 = seghead[s], a1 = seghead[s + 1];
            float sc = __int_as_float(mdc[a0].w);
            if (lane < 25) {
                float4 acc = make_float4(0.0f, 0.0f, 0.0f, 0.0f);
                for (int r = a0; r < a1; r++) {
                    float4 v = *reinterpret_cast<const float4*>(xs_c + r * 100 + 4 * lane);
                    if (do_relu) {
                        v.x = fmaxf(v.x, 0.0f); v.y = fmaxf(v.y, 0.0f);
                        v.z = fmaxf(v.z, 0.0f); v.w = fmaxf(v.w, 0.0f);
                    }
                    acc.x += v.x; acc.y += v.y; acc.z += v.z; acc.w += v.w;
                }
                float4 o;
                o.x = acc.x * sc; o.y = acc.y * sc; o.z = acc.z * sc; o.w = acc.w * sc;
                *reinterpret_cast<float4*>(xs_c + a0 * 100 + 4 * lane) = o;
            }
        }
        __syncthreads();              // sync5

        // ---- phase B: transform head rows (rel-sorted assignment) ----
        if (e < nseg) {
            int s = sseg[e];
            int h = seghead[s];
            int rel = mdc[h].z;
            float* xp = xs_c + h * 100 + b * CB;
            float xv[CB];
            const float4* xp4 = reinterpret_cast<const float4*>(xp);
#pragma unroll
            for (int k = 0; k < 5; k++) {
                float4 v = xp4[k];
                xv[4 * k + 0] = v.x; xv[4 * k + 1] = v.y;
                xv[4 * k + 2] = v.z; xv[4 * k + 3] = v.w;
            }
            const float* wb = ws + rel * WSTRIDE + b * (CB * CB);
            float acc[CB];
#pragma unroll
            for (int d = 0; d < CB; d++) acc[d] = 0.0f;
#pragma unroll
            for (int c = 0; c < CB; c++) {
                float xvc = xv[c];
                const float4* w4 = reinterpret_cast<const float4*>(wb + c * CB);
#pragma unroll
                for (int d4 = 0; d4 < 5; d4++) {
                    float4 wv = w4[d4];
                    acc[4 * d4 + 0] = fmaf(xvc, wv.x, acc[4 * d4 + 0]);
                    acc[4 * d4 + 1] = fmaf(xvc, wv.y, acc[4 * d4 + 1]);
                    acc[4 * d4 + 2] = fmaf(xvc, wv.z, acc[4 * d4 + 2]);
                    acc[4 * d4 + 3] = fmaf(xvc, wv.w, acc[4 * d4 + 3]);
                }
            }
            float4* wp = reinterpret_cast<float4*>(xp);
#pragma unroll
            for (int d4 = 0; d4 < 5; d4++) {
                float4 v;
                v.x = acc[4 * d4 + 0]; v.y = acc[4 * d4 + 1];
                v.z = acc[4 * d4 + 2]; v.w = acc[4 * d4 + 3];
                wp[d4] = v;
            }
        }
        __syncthreads();              // sync6

        // ---- phase C: per-dst-group sum of head rows + atomics ----
        for (int g = wrp; g < ndseg; g += ETHREADS / 32) {
            int s0 = dsegs[g], s1 = dsegs[g + 1];
            if (lane < 25) {
                float4 a4 = make_float4(0.0f, 0.0f, 0.0f, 0.0f);
                for (int s = s0; s < s1; s++) {
                    int h = seghead[s];
                    float4 v = *reinterpret_cast<const float4*>(xs_c + h * 100 + 4 * lane);
                    a4.x += v.x; a4.y += v.y; a4.z += v.z; a4.w += v.w;
                }
                int dst = mdc[seghead[s0]].y;
                float* op = out + (size_t)dst * HID + 4 * lane;
                atomicAdd(op + 0, a4.x);
                atomicAdd(op + 1, a4.y);
                atomicAdd(op + 2, a4.z);
                atomicAdd(op + 3, a4.w);
            }
        }
        // no trailing sync: next iteration's sync1 orders phase-C reads
        // (mdc, xs_c, seghead, dsegs, swx) before any rewrite.
        rot = (rot + 1) % 3;
        par ^= 1;
    }
}

// ---------------- host launcher ----------------
extern "C" void kernel_launch(void* const* d_in, const int* in_sizes, int n_in,
                              void* d_out, int out_size) {
    const float* node_emb = (const float*)d_in[0];
    const float* w1    = (const float*)d_in[1];
    const float* root1 = (const float*)d_in[2];
    const float* bias1 = (const float*)d_in[3];
    const float* w2    = (const float*)d_in[4];
    const float* root2 = (const float*)d_in[5];
    const float* bias2 = (const float*)d_in[6];
    const int*   eidx  = (const int*)d_in[7];
    const int*   etyp  = (const int*)d_in[8];
    float* out = (float*)d_out;

    int N = in_sizes[0] / HID;
    int E = in_sizes[8];
    if (N > MAXN) N = MAXN;
    int ntiles = (E + ETILE - 1) / ETILE;
    int Epad = ntiles * ETILE;
    if (Epad > MAXE) { Epad = MAXE; ntiles = Epad / ETILE; }

    float* h1 = nullptr;
    cudaGetSymbolAddress((void**)&h1, g_h1);

    const int EDGE_SMEM = (NREL * WSTRIDE + 2 * ETILE * 100) * 4    // ws + xs0/xs1
                        + 3 * ETILE * 16                             // meta x3
                        + (2 * (ETILE + 1) + ETILE + 96 + 96 + 20) * 4;
    const int INIT_SMEM = (GROWS * 101 + HID * HID) * 4;
    cudaFuncSetAttribute(k_edge, cudaFuncAttributeMaxDynamicSharedMemorySize, EDGE_SMEM);
    cudaFuncSetAttribute(k_init, cudaFuncAttributeMaxDynamicSharedMemorySize, INIT_SMEM);

    int RN = N * NREL;
    int nb = (RN + 1023) / 1024;     // <= 1563 (< 2048)
    int init_grid = (N + GROWS - 1) / GROWS;
    const int EDGE_GRID = 148;

    // --- preprocessing (recomputed every call; graph-capturable) ---
    k_zero<<<(RN + 255) / 256, 256>>>(RN, E, Epad);
    k_count<<<(E + 255) / 256, 256>>>(eidx, etyp, E);
    k_scan1<<<nb, 1024>>>(RN);
    k_scan2<<<1, 1024>>>(nb);
    k_scan3<<<nb, 1024>>>(RN);
    k_scatter<<<(E + 255) / 256, 256>>>(eidx, etyp, E);

    // --- layer 1: h1 = node_emb @ root1 + bias1 + block_agg(node_emb) ---
    k_init<<<init_grid, GTHREADS, INIT_SMEM>>>(node_emb, root1, bias1, h1, N, 0);
    k_edge<<<EDGE_GRID, ETHREADS, EDGE_SMEM>>>(node_emb, w1, h1, ntiles, 0);

    // --- layer 2: out = relu(h1) @ root2 + bias2 + block_agg(relu(h1)) ---
    k_init<<<init_grid, GTHREADS, INIT_SMEM>>>(h1, root2, bias2, out, N, 1);
    k_edge<<<EDGE_GRID, ETHREADS, EDGE_SMEM>>>(h1, w2, out, ntiles, 1);
}